// round 2
// baseline (speedup 1.0000x reference)
#include <cuda_runtime.h>

#define B_   4
#define T_   2048
#define C_   1024
#define H_   16
#define D_   64
#define BH_  (B_*H_)     // 64
#define M_   (B_*T_)     // 8192

// Scratch (allocation-free: __device__ globals)
__device__ float g_q [(size_t)BH_*T_*D_];   // [B,H,T,D]
__device__ float g_kT[(size_t)BH_*D_*T_];   // [B,H,D,T]  (K stored transposed)
__device__ float g_v [(size_t)BH_*T_*D_];   // [B,H,T,D]
__device__ float g_y [(size_t)M_*C_];       // [B,T,C]

// ---------------------------------------------------------------------------
// QKV GEMM: [8192,1024] x [1024,3072] + bias, epilogue scatters to q / kT / v
// 128x128 tile, BK=8, 256 threads, 8x8 per-thread microtile.
// ---------------------------------------------------------------------------
__global__ void __launch_bounds__(256) qkv_gemm_kernel(
    const float* __restrict__ X, const float* __restrict__ W,
    const float* __restrict__ bias)
{
    const int K = 1024, N = 3072;
    __shared__ float As[8][128];
    __shared__ float Bs[8][128];

    int tid = threadIdx.x;
    int tx = tid & 15, ty = tid >> 4;
    int m0 = blockIdx.y * 128;
    int n0 = blockIdx.x * 128;

    int arow = tid >> 1, acol = (tid & 1) << 2;   // A tile: 128 rows x 8 cols
    int brow = tid >> 5, bcol = (tid & 31) << 2;  // B tile: 8 rows x 128 cols

    const float* Aptr = X + (size_t)(m0 + arow) * K + acol;
    const float* Bptr = W + (size_t)brow * N + n0 + bcol;

    float acc[8][8] = {};

    for (int k0 = 0; k0 < K; k0 += 8) {
        float4 a = *(const float4*)(Aptr + k0);
        float4 b = *(const float4*)(Bptr + (size_t)k0 * N);
        As[acol+0][arow] = a.x; As[acol+1][arow] = a.y;
        As[acol+2][arow] = a.z; As[acol+3][arow] = a.w;
        *(float4*)&Bs[brow][bcol] = b;
        __syncthreads();
        #pragma unroll
        for (int kk = 0; kk < 8; kk++) {
            float ra[8], rb[8];
            *(float4*)&ra[0] = *(const float4*)&As[kk][ty*8];
            *(float4*)&ra[4] = *(const float4*)&As[kk][ty*8+4];
            *(float4*)&rb[0] = *(const float4*)&Bs[kk][tx*8];
            *(float4*)&rb[4] = *(const float4*)&Bs[kk][tx*8+4];
            #pragma unroll
            for (int i = 0; i < 8; i++)
                #pragma unroll
                for (int j = 0; j < 8; j++)
                    acc[i][j] += ra[i] * rb[j];
        }
        __syncthreads();
    }

    // Epilogue: scatter. Column block is uniform in "part" (q/k/v) and head.
    int nb = n0 + tx*8;
    int part   = nb >> 10;        // 0=q, 1=k, 2=v
    int within = nb & 1023;
    int h  = within >> 6;
    int d0 = within & 63;         // multiple of 8, stays inside one head

    float bv[8];
    #pragma unroll
    for (int j = 0; j < 8; j++) bv[j] = bias[nb + j];

    #pragma unroll
    for (int i = 0; i < 8; i++) {
        int m  = m0 + ty*8 + i;
        int bb = m >> 11, t = m & 2047;
        int bh = bb * H_ + h;
        float v[8];
        #pragma unroll
        for (int j = 0; j < 8; j++) v[j] = acc[i][j] + bv[j];

        if (part == 0) {
            float* dst = g_q + ((size_t)bh * T_ + t) * D_ + d0;
            *(float4*)dst     = make_float4(v[0], v[1], v[2], v[3]);
            *(float4*)(dst+4) = make_float4(v[4], v[5], v[6], v[7]);
        } else if (part == 2) {
            float* dst = g_v + ((size_t)bh * T_ + t) * D_ + d0;
            *(float4*)dst     = make_float4(v[0], v[1], v[2], v[3]);
            *(float4*)(dst+4) = make_float4(v[4], v[5], v[6], v[7]);
        } else {
            // K stored transposed: [bh][d][t]
            #pragma unroll
            for (int j = 0; j < 8; j++)
                g_kT[((size_t)bh * D_ + d0 + j) * T_ + t] = v[j];
        }
    }
}

// ---------------------------------------------------------------------------
// Flash attention (causal), fp32. 64x64 Q tile per block, 64-wide K/V tiles.
// 256 threads as 16x16; each thread owns a 4x4 patch of S / P / O.
// smem: sQ[q][d], sKT[d][k], sV[k][d], sP[q][k]  (each 64x64 f32, total 64KB)
// ---------------------------------------------------------------------------
__global__ void __launch_bounds__(256) attn_kernel()
{
    extern __shared__ float sm[];
    float* sQ  = sm;
    float* sKT = sm + 4096;
    float* sV  = sm + 8192;
    float* sP  = sm + 12288;

    int tid = threadIdx.x;
    int tx = tid & 15, ty = tid >> 4;
    int qt = blockIdx.x;       // query tile 0..31
    int bh = blockIdx.y;       // 0..63
    const float scale = 0.125f;  // 1/sqrt(64)

    size_t tdbase = (size_t)bh * T_ * D_;
    const float4* Qg = (const float4*)(g_q + tdbase + (size_t)qt * 64 * D_);
    #pragma unroll
    for (int i = 0; i < 4; i++)
        ((float4*)sQ)[tid + i*256] = Qg[tid + i*256];

    float o[4][4] = {};
    float mr[4] = {-1e30f, -1e30f, -1e30f, -1e30f};
    float lr[4] = {};

    const float4* KTg = (const float4*)(g_kT + (size_t)bh * D_ * T_); // row stride 512 float4
    for (int kt = 0; kt <= qt; kt++) {
        const float4* Vg = (const float4*)(g_v + tdbase + (size_t)kt * 64 * D_);
        #pragma unroll
        for (int i = 0; i < 4; i++) {
            int e = tid + i*256;          // 0..1023 float4s
            int d = e >> 4, c = e & 15;
            ((float4*)sKT)[e] = KTg[(size_t)d * 512 + kt*16 + c];
            ((float4*)sV)[e]  = Vg[e];
        }
        __syncthreads();

        // S = Q K^T
        float s[4][4] = {};
        #pragma unroll 8
        for (int d = 0; d < 64; d++) {
            float4 rk = *(const float4*)(sKT + d*64 + tx*4);
            float rq[4];
            #pragma unroll
            for (int i = 0; i < 4; i++) rq[i] = sQ[(ty*4+i)*64 + d];
            #pragma unroll
            for (int i = 0; i < 4; i++) {
                s[i][0] += rq[i]*rk.x; s[i][1] += rq[i]*rk.y;
                s[i][2] += rq[i]*rk.z; s[i][3] += rq[i]*rk.w;
            }
        }
        #pragma unroll
        for (int i = 0; i < 4; i++)
            #pragma unroll
            for (int j = 0; j < 4; j++) s[i][j] *= scale;
        if (kt == qt) {
            #pragma unroll
            for (int i = 0; i < 4; i++)
                #pragma unroll
                for (int j = 0; j < 4; j++)
                    if (tx*4 + j > ty*4 + i) s[i][j] = -1e30f;
        }

        // Online softmax (row reductions across the 16 lanes sharing ty)
        #pragma unroll
        for (int i = 0; i < 4; i++) {
            float rmax = fmaxf(fmaxf(s[i][0], s[i][1]), fmaxf(s[i][2], s[i][3]));
            #pragma unroll
            for (int off = 8; off; off >>= 1)
                rmax = fmaxf(rmax, __shfl_xor_sync(0xffffffffu, rmax, off));
            float mnew = fmaxf(mr[i], rmax);
            float corr = __expf(mr[i] - mnew);
            mr[i] = mnew;
            float4 p;
            p.x = __expf(s[i][0] - mnew);
            p.y = __expf(s[i][1] - mnew);
            p.z = __expf(s[i][2] - mnew);
            p.w = __expf(s[i][3] - mnew);
            float rsum = p.x + p.y + p.z + p.w;
            #pragma unroll
            for (int off = 8; off; off >>= 1)
                rsum += __shfl_xor_sync(0xffffffffu, rsum, off);
            lr[i] = lr[i]*corr + rsum;
            #pragma unroll
            for (int j = 0; j < 4; j++) o[i][j] *= corr;
            *(float4*)(sP + (ty*4+i)*64 + tx*4) = p;
        }
        __syncthreads();

        // O += P V
        #pragma unroll 8
        for (int k = 0; k < 64; k++) {
            float4 rv = *(const float4*)(sV + k*64 + tx*4);
            float rp[4];
            #pragma unroll
            for (int i = 0; i < 4; i++) rp[i] = sP[(ty*4+i)*64 + k];
            #pragma unroll
            for (int i = 0; i < 4; i++) {
                o[i][0] += rp[i]*rv.x; o[i][1] += rp[i]*rv.y;
                o[i][2] += rp[i]*rv.z; o[i][3] += rp[i]*rv.w;
            }
        }
        __syncthreads();   // protect sK/sV/sP overwrite next iteration
    }

    // Epilogue: O /= l, write to g_y [B,T,C] with head interleave
    int b = bh >> 4, h = bh & 15;
    #pragma unroll
    for (int i = 0; i < 4; i++) {
        float inv = 1.0f / lr[i];
        int t = qt*64 + ty*4 + i;
        float4 ov = make_float4(o[i][0]*inv, o[i][1]*inv, o[i][2]*inv, o[i][3]*inv);
        *(float4*)(g_y + ((size_t)b * T_ + t) * C_ + h*D_ + tx*4) = ov;
    }
}

// ---------------------------------------------------------------------------
// Proj GEMM: out[8192,1024] = g_y[8192,1024] x Wp[1024,1024] + bias
// ---------------------------------------------------------------------------
__global__ void __launch_bounds__(256) proj_gemm_kernel(
    const float* __restrict__ Wp, const float* __restrict__ bias,
    float* __restrict__ out)
{
    const int K = 1024, N = 1024;
    __shared__ float As[8][128];
    __shared__ float Bs[8][128];

    int tid = threadIdx.x;
    int tx = tid & 15, ty = tid >> 4;
    int m0 = blockIdx.y * 128;
    int n0 = blockIdx.x * 128;

    int arow = tid >> 1, acol = (tid & 1) << 2;
    int brow = tid >> 5, bcol = (tid & 31) << 2;

    const float* Aptr = g_y + (size_t)(m0 + arow) * K + acol;
    const float* Bptr = Wp + (size_t)brow * N + n0 + bcol;

    float acc[8][8] = {};

    for (int k0 = 0; k0 < K; k0 += 8) {
        float4 a = *(const float4*)(Aptr + k0);
        float4 b = *(const float4*)(Bptr + (size_t)k0 * N);
        As[acol+0][arow] = a.x; As[acol+1][arow] = a.y;
        As[acol+2][arow] = a.z; As[acol+3][arow] = a.w;
        *(float4*)&Bs[brow][bcol] = b;
        __syncthreads();
        #pragma unroll
        for (int kk = 0; kk < 8; kk++) {
            float ra[8], rb[8];
            *(float4*)&ra[0] = *(const float4*)&As[kk][ty*8];
            *(float4*)&ra[4] = *(const float4*)&As[kk][ty*8+4];
            *(float4*)&rb[0] = *(const float4*)&Bs[kk][tx*8];
            *(float4*)&rb[4] = *(const float4*)&Bs[kk][tx*8+4];
            #pragma unroll
            for (int i = 0; i < 8; i++)
                #pragma unroll
                for (int j = 0; j < 8; j++)
                    acc[i][j] += ra[i] * rb[j];
        }
        __syncthreads();
    }

    int nb = n0 + tx*8;
    float bv[8];
    #pragma unroll
    for (int j = 0; j < 8; j++) bv[j] = bias[nb + j];

    #pragma unroll
    for (int i = 0; i < 8; i++) {
        int m = m0 + ty*8 + i;
        float* dst = out + (size_t)m * N + nb;
        *(float4*)dst = make_float4(acc[i][0]+bv[0], acc[i][1]+bv[1],
                                    acc[i][2]+bv[2], acc[i][3]+bv[3]);
        *(float4*)(dst+4) = make_float4(acc[i][4]+bv[4], acc[i][5]+bv[5],
                                        acc[i][6]+bv[6], acc[i][7]+bv[7]);
    }
}

// ---------------------------------------------------------------------------
extern "C" void kernel_launch(void* const* d_in, const int* in_sizes, int n_in,
                              void* d_out, int out_size)
{
    const float* x      = (const float*)d_in[0];
    const float* w_attn = (const float*)d_in[1];
    const float* b_attn = (const float*)d_in[2];
    const float* w_proj = (const float*)d_in[3];
    const float* b_proj = (const float*)d_in[4];
    float* out = (float*)d_out;

    (void)in_sizes; (void)n_in; (void)out_size;

    cudaFuncSetAttribute(attn_kernel,
                         cudaFuncAttributeMaxDynamicSharedMemorySize, 65536);

    qkv_gemm_kernel<<<dim3(24, 64), 256>>>(x, w_attn, b_attn);
    attn_kernel<<<dim3(32, 64), 256, 65536>>>();
    proj_gemm_kernel<<<dim3(8, 64), 256>>>(w_proj, b_proj, out);
}

// round 3
// speedup vs baseline: 2.2906x; 2.2906x over previous
#include <cuda_runtime.h>
#include <cuda_bf16.h>
#include <cstdint>

#define B_   4
#define T_   2048
#define C_   1024
#define H_   16
#define D_   64
#define BH_  64
#define M_   8192

typedef __nv_bfloat16 bf16;
typedef __nv_bfloat162 bf162;

// ---------------- scratch (allocation-free) ----------------
__device__ bf16 g_xh[(size_t)M_*C_],    g_xl[(size_t)M_*C_];
__device__ bf16 g_wah[(size_t)C_*3*C_], g_wal[(size_t)C_*3*C_];
__device__ bf16 g_wph[(size_t)C_*C_],   g_wpl[(size_t)C_*C_];
__device__ bf16 g_qkvh[(size_t)3*BH_*T_*D_], g_qkvl[(size_t)3*BH_*T_*D_];
__device__ bf16 g_yh[(size_t)M_*C_],    g_yl[(size_t)M_*C_];

#define DI static __device__ __forceinline__

DI uint32_t smaddr(const void* p){ return (uint32_t)__cvta_generic_to_shared(p); }

DI void ldm_x4(uint32_t* r, uint32_t a){
    asm volatile("ldmatrix.sync.aligned.m8n8.x4.shared.b16 {%0,%1,%2,%3},[%4];"
        :"=r"(r[0]),"=r"(r[1]),"=r"(r[2]),"=r"(r[3]):"r"(a));
}
DI void ldm_x4t(uint32_t* r, uint32_t a){
    asm volatile("ldmatrix.sync.aligned.m8n8.x4.trans.shared.b16 {%0,%1,%2,%3},[%4];"
        :"=r"(r[0]),"=r"(r[1]),"=r"(r[2]),"=r"(r[3]):"r"(a));
}
DI void mma16816(float* c, const uint32_t* a, uint32_t b0, uint32_t b1){
    asm volatile("mma.sync.aligned.m16n8k16.row.col.f32.bf16.bf16.f32 "
        "{%0,%1,%2,%3},{%4,%5,%6,%7},{%8,%9},{%0,%1,%2,%3};"
        :"+f"(c[0]),"+f"(c[1]),"+f"(c[2]),"+f"(c[3])
        :"r"(a[0]),"r"(a[1]),"r"(a[2]),"r"(a[3]),"r"(b0),"r"(b1));
}
DI uint32_t pk2(bf16 a, bf16 b){
    bf162 t = __halves2bfloat162(a, b);
    return *reinterpret_cast<uint32_t*>(&t);
}
DI uint32_t pkf2(float x, float y){
    bf162 t = __floats2bfloat162_rn(x, y);
    return *reinterpret_cast<uint32_t*>(&t);
}

// ---------------------------------------------------------------------------
// Split fp32 -> (hi, lo) bf16 pair.  mode: 0=x, 1=w_attn, 2=w_proj
// ---------------------------------------------------------------------------
__global__ void split_kernel(const float4* __restrict__ src, int mode, int n4)
{
    int i = blockIdx.x*256 + threadIdx.x;
    if (i >= n4) return;
    bf16 *hi, *lo;
    if (mode == 0)      { hi = g_xh;  lo = g_xl;  }
    else if (mode == 1) { hi = g_wah; lo = g_wal; }
    else                { hi = g_wph; lo = g_wpl; }
    float4 v = src[i];
    bf16 h0=__float2bfloat16(v.x), h1=__float2bfloat16(v.y),
         h2=__float2bfloat16(v.z), h3=__float2bfloat16(v.w);
    uint2 hp = make_uint2(pk2(h0,h1), pk2(h2,h3));
    uint2 lp = make_uint2(pkf2(v.x-__bfloat162float(h0), v.y-__bfloat162float(h1)),
                          pkf2(v.z-__bfloat162float(h2), v.w-__bfloat162float(h3)));
    *reinterpret_cast<uint2*>(hi + (size_t)i*4) = hp;
    *reinterpret_cast<uint2*>(lo + (size_t)i*4) = lp;
}

// ---------------------------------------------------------------------------
// Split-bf16 GEMM via mma.sync.  128x128 block tile, BK=32, 8 warps (2x4),
// warp tile 64x32.  mode 0: X @ W_attn -> scatter split q/k/v (scale q by 1/8)
//                   mode 1: Y @ W_proj -> fp32 out + bias
// ---------------------------------------------------------------------------
__global__ void __launch_bounds__(256,1) gemm_split_kernel(
    int mode, const float* __restrict__ bias, float* __restrict__ out)
{
    const int N = mode ? 1024 : 3072;
    const bf16* __restrict__ Ah = mode ? g_yh  : g_xh;
    const bf16* __restrict__ Al = mode ? g_yl  : g_xl;
    const bf16* __restrict__ Bh = mode ? g_wph : g_wah;
    const bf16* __restrict__ Bl = mode ? g_wpl : g_wal;

    __shared__ bf16 sAh[128*40], sAl[128*40], sBh[32*136], sBl[32*136];

    int tid = threadIdx.x, lane = tid & 31, wid = tid >> 5;
    int wm = wid >> 2, wn = wid & 3;
    int m0 = blockIdx.y * 128, n0 = blockIdx.x * 128;

    float acc[4][4][4];
    #pragma unroll
    for (int a = 0; a < 4; a++)
        #pragma unroll
        for (int b = 0; b < 4; b++)
            #pragma unroll
            for (int c = 0; c < 4; c++) acc[a][b][c] = 0.f;

    int lr = lane & 15, lc = lane >> 4;

    for (int k0 = 0; k0 < 1024; k0 += 32) {
        #pragma unroll
        for (int q = 0; q < 2; q++) {
            int c = tid + q*256;
            int ar = c >> 2, aoff = (c & 3) << 3;
            size_t asrc = (size_t)(m0 + ar)*1024 + k0 + aoff;
            *(uint4*)(sAh + ar*40 + aoff) = *(const uint4*)(Ah + asrc);
            *(uint4*)(sAl + ar*40 + aoff) = *(const uint4*)(Al + asrc);
            int br = c >> 4, boff = (c & 15) << 3;
            size_t bsrc = (size_t)(k0 + br)*N + n0 + boff;
            *(uint4*)(sBh + br*136 + boff) = *(const uint4*)(Bh + bsrc);
            *(uint4*)(sBl + br*136 + boff) = *(const uint4*)(Bl + bsrc);
        }
        __syncthreads();
        #pragma unroll
        for (int kk = 0; kk < 32; kk += 16) {
            uint32_t ah[4][4], al[4][4], bh[4][2], bl[4][2];
            #pragma unroll
            for (int mi = 0; mi < 4; mi++) {
                int ro = (wm*64 + mi*16 + lr)*40 + kk + lc*8;
                ldm_x4(ah[mi], smaddr(sAh + ro));
                ldm_x4(al[mi], smaddr(sAl + ro));
            }
            #pragma unroll
            for (int p = 0; p < 2; p++) {
                uint32_t t[4];
                int ro = (kk + lr)*136 + wn*32 + p*16 + lc*8;
                ldm_x4t(t, smaddr(sBh + ro));
                bh[2*p][0]=t[0]; bh[2*p][1]=t[1]; bh[2*p+1][0]=t[2]; bh[2*p+1][1]=t[3];
                ldm_x4t(t, smaddr(sBl + ro));
                bl[2*p][0]=t[0]; bl[2*p][1]=t[1]; bl[2*p+1][0]=t[2]; bl[2*p+1][1]=t[3];
            }
            #pragma unroll
            for (int mi = 0; mi < 4; mi++)
                #pragma unroll
                for (int ni = 0; ni < 4; ni++) {
                    mma16816(acc[mi][ni], ah[mi], bh[ni][0], bh[ni][1]);
                    mma16816(acc[mi][ni], ah[mi], bl[ni][0], bl[ni][1]);
                    mma16816(acc[mi][ni], al[mi], bh[ni][0], bh[ni][1]);
                }
        }
        __syncthreads();
    }

    int lr4 = lane >> 2, lc2 = (lane & 3) << 1;
    if (mode == 0) {
        #pragma unroll
        for (int mi = 0; mi < 4; mi++) {
            int r0 = m0 + wm*64 + mi*16 + lr4;
            #pragma unroll
            for (int ni = 0; ni < 4; ni++) {
                int col = n0 + wn*32 + ni*8 + lc2;
                float b0v = bias[col], b1v = bias[col+1];
                int part = col >> 10, within = col & 1023;
                int h = within >> 6, d = within & 63;
                float sc = (part == 0) ? 0.125f : 1.0f;   // fold softmax scale into Q (exact)
                #pragma unroll
                for (int e = 0; e < 2; e++) {
                    int r = r0 + e*8;
                    int bb = r >> 11, t = r & 2047;
                    size_t idx = (((size_t)part*BH_ + bb*H_ + h)*T_ + t)*D_ + d;
                    float v0 = (acc[mi][ni][2*e]   + b0v)*sc;
                    float v1 = (acc[mi][ni][2*e+1] + b1v)*sc;
                    bf16 h0 = __float2bfloat16(v0), h1 = __float2bfloat16(v1);
                    *(uint32_t*)(g_qkvh + idx) = pk2(h0, h1);
                    *(uint32_t*)(g_qkvl + idx) =
                        pkf2(v0-__bfloat162float(h0), v1-__bfloat162float(h1));
                }
            }
        }
    } else {
        #pragma unroll
        for (int mi = 0; mi < 4; mi++) {
            int r0 = m0 + wm*64 + mi*16 + lr4;
            #pragma unroll
            for (int ni = 0; ni < 4; ni++) {
                int col = n0 + wn*32 + ni*8 + lc2;
                float b0v = bias[col], b1v = bias[col+1];
                #pragma unroll
                for (int e = 0; e < 2; e++) {
                    int r = r0 + e*8;
                    float2 v = make_float2(acc[mi][ni][2*e] + b0v,
                                           acc[mi][ni][2*e+1] + b1v);
                    *(float2*)(out + (size_t)r*1024 + col) = v;
                }
            }
        }
    }
}

// ---------------------------------------------------------------------------
// FlashAttention-2, split-bf16 tensor cores.  128-row Q tile, 8 warps
// (16 rows each, full D=64), 64-wide K/V tiles, P register-resident.
// ---------------------------------------------------------------------------
__global__ void __launch_bounds__(256,1) attn_kernel()
{
    __shared__ bf16 smem_[2*128*72];
    bf16* sQh = smem_;
    bf16* sQl = smem_ + 128*72;
    bf16* sKh = smem_;                 // reuses Q staging after frags loaded
    bf16* sKl = smem_ + 64*72;
    bf16* sVh = smem_ + 2*64*72;
    bf16* sVl = smem_ + 3*64*72;

    int tid = threadIdx.x, lane = tid & 31, w = tid >> 5;
    int qt = 15 - (int)blockIdx.x;     // big tiles first
    int bh = blockIdx.y;

    const bf16* Qh = g_qkvh + (size_t)bh*T_*D_ + (size_t)qt*128*D_;
    const bf16* Ql = g_qkvl + (size_t)bh*T_*D_ + (size_t)qt*128*D_;
    const bf16* Kh = g_qkvh + ((size_t)BH_   + bh)*T_*D_;
    const bf16* Kl = g_qkvl + ((size_t)BH_   + bh)*T_*D_;
    const bf16* Vh = g_qkvh + ((size_t)2*BH_ + bh)*T_*D_;
    const bf16* Vl = g_qkvl + ((size_t)2*BH_ + bh)*T_*D_;

    // stage Q tile, pull A-fragments into registers, then free the smem
    #pragma unroll
    for (int q = 0; q < 4; q++) {
        int c = tid + q*256;
        int r = c >> 3, off = (c & 7) << 3;
        *(uint4*)(sQh + r*72 + off) = *(const uint4*)(Qh + (size_t)r*64 + off);
        *(uint4*)(sQl + r*72 + off) = *(const uint4*)(Ql + (size_t)r*64 + off);
    }
    __syncthreads();
    int lr = lane & 15, lc = lane >> 4;
    uint32_t qh[4][4], ql[4][4];
    #pragma unroll
    for (int kk = 0; kk < 4; kk++) {
        int ro = (w*16 + lr)*72 + kk*16 + lc*8;
        ldm_x4(qh[kk], smaddr(sQh + ro));
        ldm_x4(ql[kk], smaddr(sQl + ro));
    }
    __syncthreads();

    float o[8][4];
    #pragma unroll
    for (int j = 0; j < 8; j++)
        #pragma unroll
        for (int e = 0; e < 4; e++) o[j][e] = 0.f;
    float mrow[2] = {-1e30f, -1e30f}, lrow[2] = {0.f, 0.f};

    int kend = 2*qt + 1;
    for (int kt = 0; kt <= kend; kt++) {
        const bf16* kh = Kh + (size_t)kt*64*D_;
        const bf16* kl = Kl + (size_t)kt*64*D_;
        const bf16* vh = Vh + (size_t)kt*64*D_;
        const bf16* vl = Vl + (size_t)kt*64*D_;
        #pragma unroll
        for (int q = 0; q < 2; q++) {
            int c = tid + q*256;
            int r = c >> 3, off = (c & 7) << 3;
            size_t s = (size_t)r*64 + off;
            int ds = r*72 + off;
            *(uint4*)(sKh + ds) = *(const uint4*)(kh + s);
            *(uint4*)(sKl + ds) = *(const uint4*)(kl + s);
            *(uint4*)(sVh + ds) = *(const uint4*)(vh + s);
            *(uint4*)(sVl + ds) = *(const uint4*)(vl + s);
        }
        __syncthreads();

        // S = Q K^T (split: hi*hi + hi*lo + lo*hi)
        float s[8][4];
        #pragma unroll
        for (int j = 0; j < 8; j++)
            #pragma unroll
            for (int e = 0; e < 4; e++) s[j][e] = 0.f;
        #pragma unroll
        for (int kk = 0; kk < 4; kk++) {
            #pragma unroll
            for (int p2 = 0; p2 < 4; p2++) {
                uint32_t kfh[4], kfl[4];
                int nrow = p2*16 + lc*8 + (lane & 7);
                int koff = kk*16 + ((lane >> 3) & 1)*8;
                ldm_x4(kfh, smaddr(sKh + nrow*72 + koff));
                ldm_x4(kfl, smaddr(sKl + nrow*72 + koff));
                mma16816(s[2*p2],   qh[kk], kfh[0], kfh[1]);
                mma16816(s[2*p2],   qh[kk], kfl[0], kfl[1]);
                mma16816(s[2*p2],   ql[kk], kfh[0], kfh[1]);
                mma16816(s[2*p2+1], qh[kk], kfh[2], kfh[3]);
                mma16816(s[2*p2+1], qh[kk], kfl[2], kfl[3]);
                mma16816(s[2*p2+1], ql[kk], kfh[2], kfh[3]);
            }
        }

        if (kt >= 2*qt) {   // only the last two tiles can touch the diagonal
            int rowb = qt*128 + w*16 + (lane >> 2);
            int colb = kt*64 + ((lane & 3) << 1);
            #pragma unroll
            for (int j = 0; j < 8; j++)
                #pragma unroll
                for (int e = 0; e < 4; e++) {
                    int row = rowb + (e >> 1)*8;
                    int col = colb + j*8 + (e & 1);
                    if (col > row) s[j][e] = -1e30f;
                }
        }

        // online softmax; rows r (regs 0,1) and r+8 (regs 2,3)
        #pragma unroll
        for (int e = 0; e < 2; e++) {
            float mx = -1e30f;
            #pragma unroll
            for (int j = 0; j < 8; j++)
                mx = fmaxf(mx, fmaxf(s[j][2*e], s[j][2*e+1]));
            mx = fmaxf(mx, __shfl_xor_sync(0xffffffffu, mx, 1));
            mx = fmaxf(mx, __shfl_xor_sync(0xffffffffu, mx, 2));
            float mn = fmaxf(mrow[e], mx);
            float corr = __expf(mrow[e] - mn);
            mrow[e] = mn;
            float sum = 0.f;
            #pragma unroll
            for (int j = 0; j < 8; j++) {
                float p0 = __expf(s[j][2*e]   - mn);
                float p1 = __expf(s[j][2*e+1] - mn);
                s[j][2*e] = p0; s[j][2*e+1] = p1;
                sum += p0 + p1;
            }
            sum += __shfl_xor_sync(0xffffffffu, sum, 1);
            sum += __shfl_xor_sync(0xffffffffu, sum, 2);
            lrow[e] = lrow[e]*corr + sum;
            #pragma unroll
            for (int j = 0; j < 8; j++) { o[j][2*e] *= corr; o[j][2*e+1] *= corr; }
        }

        // O += P V (split), P built from S accumulators in-register
        #pragma unroll
        for (int kk = 0; kk < 4; kk++) {
            uint32_t ph[4], pl[4];
            #pragma unroll
            for (int u = 0; u < 2; u++) {
                float x0=s[2*kk+u][0], x1=s[2*kk+u][1], x2=s[2*kk+u][2], x3=s[2*kk+u][3];
                bf16 h0=__float2bfloat16(x0), h1=__float2bfloat16(x1);
                bf16 h2=__float2bfloat16(x2), h3=__float2bfloat16(x3);
                ph[2*u]   = pk2(h0, h1);
                ph[2*u+1] = pk2(h2, h3);
                pl[2*u]   = pkf2(x0-__bfloat162float(h0), x1-__bfloat162float(h1));
                pl[2*u+1] = pkf2(x2-__bfloat162float(h2), x3-__bfloat162float(h3));
            }
            #pragma unroll
            for (int p2 = 0; p2 < 4; p2++) {
                uint32_t vfh[4], vfl[4];
                int ro = (kk*16 + lr)*72 + p2*16 + lc*8;
                ldm_x4t(vfh, smaddr(sVh + ro));
                ldm_x4t(vfl, smaddr(sVl + ro));
                mma16816(o[2*p2],   ph, vfh[0], vfh[1]);
                mma16816(o[2*p2],   ph, vfl[0], vfl[1]);
                mma16816(o[2*p2],   pl, vfh[0], vfh[1]);
                mma16816(o[2*p2+1], ph, vfh[2], vfh[3]);
                mma16816(o[2*p2+1], ph, vfl[2], vfl[3]);
                mma16816(o[2*p2+1], pl, vfh[2], vfh[3]);
            }
        }
        __syncthreads();
    }

    // epilogue: y = O / l, write pre-split for proj GEMM
    int b = bh >> 4, h = bh & 15;
    #pragma unroll
    for (int e = 0; e < 2; e++) {
        float inv = 1.f / lrow[e];
        int t = qt*128 + w*16 + (lane >> 2) + e*8;
        bf16* yh = g_yh + ((size_t)b*T_ + t)*C_ + h*64;
        bf16* yl = g_yl + ((size_t)b*T_ + t)*C_ + h*64;
        #pragma unroll
        for (int j = 0; j < 8; j++) {
            int d = j*8 + ((lane & 3) << 1);
            float v0 = o[j][2*e]*inv, v1 = o[j][2*e+1]*inv;
            bf16 h0 = __float2bfloat16(v0), h1 = __float2bfloat16(v1);
            *(uint32_t*)(yh + d) = pk2(h0, h1);
            *(uint32_t*)(yl + d) = pkf2(v0-__bfloat162float(h0), v1-__bfloat162float(h1));
        }
    }
}

// ---------------------------------------------------------------------------
extern "C" void kernel_launch(void* const* d_in, const int* in_sizes, int n_in,
                              void* d_out, int out_size)
{
    const float* x      = (const float*)d_in[0];
    const float* w_attn = (const float*)d_in[1];
    const float* b_attn = (const float*)d_in[2];
    const float* w_proj = (const float*)d_in[3];
    const float* b_proj = (const float*)d_in[4];
    float* out = (float*)d_out;
    (void)in_sizes; (void)n_in; (void)out_size;

    split_kernel<<<8192, 256>>>((const float4*)x,      0, 2097152);
    split_kernel<<<3072, 256>>>((const float4*)w_attn, 1,  786432);
    split_kernel<<<1024, 256>>>((const float4*)w_proj, 2,  262144);
    gemm_split_kernel<<<dim3(24, 64), 256>>>(0, b_attn, nullptr);
    attn_kernel<<<dim3(16, 64), 256>>>();
    gemm_split_kernel<<<dim3(8, 64), 256>>>(1, b_proj, out);
}

// round 4
// speedup vs baseline: 2.6230x; 1.1451x over previous
#include <cuda_runtime.h>
#include <cuda_bf16.h>
#include <cstdint>

#define B_   4
#define T_   2048
#define C_   1024
#define H_   16
#define D_   64
#define BH_  64
#define M_   8192

typedef __nv_bfloat16 bf16;
typedef __nv_bfloat162 bf162;

// ---------------- scratch (allocation-free) ----------------
__device__ bf16 g_xh[(size_t)M_*C_],    g_xl[(size_t)M_*C_];
__device__ bf16 g_wah[(size_t)C_*3*C_], g_wal[(size_t)C_*3*C_];
__device__ bf16 g_wph[(size_t)C_*C_],   g_wpl[(size_t)C_*C_];
__device__ bf16 g_qkvh[(size_t)3*BH_*T_*D_], g_qkvl[(size_t)3*BH_*T_*D_];
__device__ bf16 g_yh[(size_t)M_*C_],    g_yl[(size_t)M_*C_];

#define DI static __device__ __forceinline__

DI uint32_t smaddr(const void* p){ return (uint32_t)__cvta_generic_to_shared(p); }

DI void cpa16(void* dst, const void* src){
    asm volatile("cp.async.cg.shared.global [%0],[%1],16;\n"
        ::"r"(smaddr(dst)),"l"(src));
}
DI void cpcommit(){ asm volatile("cp.async.commit_group;\n"); }
template<int N> DI void cpwait(){ asm volatile("cp.async.wait_group %0;\n"::"n"(N)); }

DI void ldm_x4(uint32_t* r, uint32_t a){
    asm volatile("ldmatrix.sync.aligned.m8n8.x4.shared.b16 {%0,%1,%2,%3},[%4];"
        :"=r"(r[0]),"=r"(r[1]),"=r"(r[2]),"=r"(r[3]):"r"(a));
}
DI void ldm_x4t(uint32_t* r, uint32_t a){
    asm volatile("ldmatrix.sync.aligned.m8n8.x4.trans.shared.b16 {%0,%1,%2,%3},[%4];"
        :"=r"(r[0]),"=r"(r[1]),"=r"(r[2]),"=r"(r[3]):"r"(a));
}
DI void mma16816(float* c, const uint32_t* a, uint32_t b0, uint32_t b1){
    asm volatile("mma.sync.aligned.m16n8k16.row.col.f32.bf16.bf16.f32 "
        "{%0,%1,%2,%3},{%4,%5,%6,%7},{%8,%9},{%0,%1,%2,%3};"
        :"+f"(c[0]),"+f"(c[1]),"+f"(c[2]),"+f"(c[3])
        :"r"(a[0]),"r"(a[1]),"r"(a[2]),"r"(a[3]),"r"(b0),"r"(b1));
}
DI uint32_t pk2(bf16 a, bf16 b){
    bf162 t = __halves2bfloat162(a, b);
    return *reinterpret_cast<uint32_t*>(&t);
}
DI uint32_t pkf2(float x, float y){
    bf162 t = __floats2bfloat162_rn(x, y);
    return *reinterpret_cast<uint32_t*>(&t);
}

// ---------------------------------------------------------------------------
// Split fp32 -> (hi, lo) bf16 pair.  mode: 0=x, 1=w_attn, 2=w_proj
// ---------------------------------------------------------------------------
__global__ void split_kernel(const float4* __restrict__ src, int mode, int n4)
{
    int i = blockIdx.x*256 + threadIdx.x;
    if (i >= n4) return;
    bf16 *hi, *lo;
    if (mode == 0)      { hi = g_xh;  lo = g_xl;  }
    else if (mode == 1) { hi = g_wah; lo = g_wal; }
    else                { hi = g_wph; lo = g_wpl; }
    float4 v = src[i];
    bf16 h0=__float2bfloat16(v.x), h1=__float2bfloat16(v.y),
         h2=__float2bfloat16(v.z), h3=__float2bfloat16(v.w);
    uint2 hp = make_uint2(pk2(h0,h1), pk2(h2,h3));
    uint2 lp = make_uint2(pkf2(v.x-__bfloat162float(h0), v.y-__bfloat162float(h1)),
                          pkf2(v.z-__bfloat162float(h2), v.w-__bfloat162float(h3)));
    *reinterpret_cast<uint2*>(hi + (size_t)i*4) = hp;
    *reinterpret_cast<uint2*>(lo + (size_t)i*4) = lp;
}

// ---------------------------------------------------------------------------
// Split-bf16 GEMM, 2-stage cp.async pipeline.  128x128 tile, BK=32, 8 warps.
// mode 0: X @ W_attn -> scatter split q/k/v (softmax scale folded into Q)
// mode 1: Y @ W_proj -> fp32 out + bias
// ---------------------------------------------------------------------------
#define ASZ (128*40)
#define BSZ (32*136)
#define GSTG (2*ASZ + 2*BSZ)

__global__ void __launch_bounds__(256,1) gemm_split_kernel(
    int mode, const float* __restrict__ bias, float* __restrict__ out)
{
    const int N = mode ? 1024 : 3072;
    const bf16* __restrict__ Ah = mode ? g_yh  : g_xh;
    const bf16* __restrict__ Al = mode ? g_yl  : g_xl;
    const bf16* __restrict__ Bh = mode ? g_wph : g_wah;
    const bf16* __restrict__ Bl = mode ? g_wpl : g_wal;

    extern __shared__ bf16 dyn[];

    int tid = threadIdx.x, lane = tid & 31, wid = tid >> 5;
    int wm = wid >> 2, wn = wid & 3;
    int m0 = blockIdx.y * 128, n0 = blockIdx.x * 128;

    float acc[4][4][4];
    #pragma unroll
    for (int a = 0; a < 4; a++)
        #pragma unroll
        for (int b = 0; b < 4; b++)
            #pragma unroll
            for (int c = 0; c < 4; c++) acc[a][b][c] = 0.f;

    int lr = lane & 15, lc = lane >> 4;

    int ar = tid >> 1, aoff = (tid & 1) << 4;          // 128 rows x 32 cols, 2x16B
    int br = tid >> 4, boff = (tid & 15) << 3;         // 32 rows x 128 cols, 16B

    auto load_stage = [&](int st, int k0){
        bf16* ah = dyn + st*GSTG;
        bf16* al = ah + ASZ;
        bf16* bh2 = al + ASZ;
        bf16* bl2 = bh2 + BSZ;
        size_t asrc = (size_t)(m0 + ar)*1024 + k0 + aoff;
        cpa16(ah + ar*40 + aoff,     Ah + asrc);
        cpa16(ah + ar*40 + aoff + 8, Ah + asrc + 8);
        cpa16(al + ar*40 + aoff,     Al + asrc);
        cpa16(al + ar*40 + aoff + 8, Al + asrc + 8);
        size_t bsrc = (size_t)(k0 + br)*N + n0 + boff;
        size_t bsrc2 = bsrc + (size_t)16*N;
        cpa16(bh2 + br*136 + boff,        Bh + bsrc);
        cpa16(bh2 + (br+16)*136 + boff,   Bh + bsrc2);
        cpa16(bl2 + br*136 + boff,        Bl + bsrc);
        cpa16(bl2 + (br+16)*136 + boff,   Bl + bsrc2);
        cpcommit();
    };

    load_stage(0, 0);

    for (int t = 0; t < 32; t++) {
        int cur = t & 1;
        if (t < 31) load_stage(cur ^ 1, (t+1)*32);
        if (t < 31) cpwait<1>(); else cpwait<0>();
        __syncthreads();

        bf16* sAh = dyn + cur*GSTG;
        bf16* sAl = sAh + ASZ;
        bf16* sBh = sAl + ASZ;
        bf16* sBl = sBh + BSZ;

        #pragma unroll
        for (int kk = 0; kk < 32; kk += 16) {
            uint32_t ah[4][4], al[4][4], bh[4][2], bl[4][2];
            #pragma unroll
            for (int mi = 0; mi < 4; mi++) {
                int ro = (wm*64 + mi*16 + lr)*40 + kk + lc*8;
                ldm_x4(ah[mi], smaddr(sAh + ro));
                ldm_x4(al[mi], smaddr(sAl + ro));
            }
            #pragma unroll
            for (int p = 0; p < 2; p++) {
                uint32_t tt[4];
                int ro = (kk + lr)*136 + wn*32 + p*16 + lc*8;
                ldm_x4t(tt, smaddr(sBh + ro));
                bh[2*p][0]=tt[0]; bh[2*p][1]=tt[1]; bh[2*p+1][0]=tt[2]; bh[2*p+1][1]=tt[3];
                ldm_x4t(tt, smaddr(sBl + ro));
                bl[2*p][0]=tt[0]; bl[2*p][1]=tt[1]; bl[2*p+1][0]=tt[2]; bl[2*p+1][1]=tt[3];
            }
            #pragma unroll
            for (int mi = 0; mi < 4; mi++)
                #pragma unroll
                for (int ni = 0; ni < 4; ni++) {
                    mma16816(acc[mi][ni], ah[mi], bh[ni][0], bh[ni][1]);
                    mma16816(acc[mi][ni], ah[mi], bl[ni][0], bl[ni][1]);
                    mma16816(acc[mi][ni], al[mi], bh[ni][0], bh[ni][1]);
                }
        }
        __syncthreads();
    }

    int lr4 = lane >> 2, lc2 = (lane & 3) << 1;
    if (mode == 0) {
        #pragma unroll
        for (int mi = 0; mi < 4; mi++) {
            int r0 = m0 + wm*64 + mi*16 + lr4;
            #pragma unroll
            for (int ni = 0; ni < 4; ni++) {
                int col = n0 + wn*32 + ni*8 + lc2;
                float b0v = bias[col], b1v = bias[col+1];
                int part = col >> 10, within = col & 1023;
                int h = within >> 6, d = within & 63;
                float sc = (part == 0) ? 0.125f : 1.0f;
                #pragma unroll
                for (int e = 0; e < 2; e++) {
                    int r = r0 + e*8;
                    int bb = r >> 11, t = r & 2047;
                    size_t idx = (((size_t)part*BH_ + bb*H_ + h)*T_ + t)*D_ + d;
                    float v0 = (acc[mi][ni][2*e]   + b0v)*sc;
                    float v1 = (acc[mi][ni][2*e+1] + b1v)*sc;
                    bf16 h0 = __float2bfloat16(v0), h1 = __float2bfloat16(v1);
                    *(uint32_t*)(g_qkvh + idx) = pk2(h0, h1);
                    *(uint32_t*)(g_qkvl + idx) =
                        pkf2(v0-__bfloat162float(h0), v1-__bfloat162float(h1));
                }
            }
        }
    } else {
        #pragma unroll
        for (int mi = 0; mi < 4; mi++) {
            int r0 = m0 + wm*64 + mi*16 + lr4;
            #pragma unroll
            for (int ni = 0; ni < 4; ni++) {
                int col = n0 + wn*32 + ni*8 + lc2;
                float b0v = bias[col], b1v = bias[col+1];
                #pragma unroll
                for (int e = 0; e < 2; e++) {
                    int r = r0 + e*8;
                    float2 v = make_float2(acc[mi][ni][2*e] + b0v,
                                           acc[mi][ni][2*e+1] + b1v);
                    *(float2*)(out + (size_t)r*1024 + col) = v;
                }
            }
        }
    }
}

// ---------------------------------------------------------------------------
// FlashAttention-2, split-bf16, 2-stage cp.async K/V pipeline.
// 128-row Q tile, 8 warps, 64-wide K/V tiles, P register-resident.
// ---------------------------------------------------------------------------
#define KSZ (64*72)
#define ASTG (4*KSZ)   // kh,kl,vh,vl per stage

__global__ void __launch_bounds__(256,1) attn_kernel()
{
    extern __shared__ bf16 dyn[];   // 2*ASTG bf16 = 73728 B

    int tid = threadIdx.x, lane = tid & 31, w = tid >> 5;
    int qt = 15 - (int)blockIdx.x;
    int bh = blockIdx.y;

    const bf16* Qh = g_qkvh + (size_t)bh*T_*D_ + (size_t)qt*128*D_;
    const bf16* Ql = g_qkvl + (size_t)bh*T_*D_ + (size_t)qt*128*D_;
    const bf16* Kh = g_qkvh + ((size_t)BH_   + bh)*T_*D_;
    const bf16* Kl = g_qkvl + ((size_t)BH_   + bh)*T_*D_;
    const bf16* Vh = g_qkvh + ((size_t)2*BH_ + bh)*T_*D_;
    const bf16* Vl = g_qkvl + ((size_t)2*BH_ + bh)*T_*D_;

    // stage Q in smem (overlaps stage buffers, consumed before K/V prologue)
    bf16* sQh = dyn;
    bf16* sQl = dyn + 128*72;
    #pragma unroll
    for (int q = 0; q < 4; q++) {
        int c = tid + q*256;
        int r = c >> 3, off = (c & 7) << 3;
        size_t s = (size_t)r*64 + off;
        cpa16(sQh + r*72 + off, Qh + s);
        cpa16(sQl + r*72 + off, Ql + s);
    }
    cpcommit();
    cpwait<0>();
    __syncthreads();

    int lr = lane & 15, lc = lane >> 4;
    uint32_t qh[4][4], ql[4][4];
    #pragma unroll
    for (int kk = 0; kk < 4; kk++) {
        int ro = (w*16 + lr)*72 + kk*16 + lc*8;
        ldm_x4(qh[kk], smaddr(sQh + ro));
        ldm_x4(ql[kk], smaddr(sQl + ro));
    }
    __syncthreads();   // everyone done with Q staging before K/V overwrites

    auto load_kv = [&](int st, int kt){
        bf16* kh2 = dyn + st*ASTG;
        bf16* kl2 = kh2 + KSZ;
        bf16* vh2 = kl2 + KSZ;
        bf16* vl2 = vh2 + KSZ;
        size_t base = (size_t)kt*64*D_;
        #pragma unroll
        for (int q = 0; q < 2; q++) {
            int c = tid + q*256;
            int r = c >> 3, off = (c & 7) << 3;
            size_t s = base + (size_t)r*64 + off;
            int ds = r*72 + off;
            cpa16(kh2 + ds, Kh + s);
            cpa16(kl2 + ds, Kl + s);
            cpa16(vh2 + ds, Vh + s);
            cpa16(vl2 + ds, Vl + s);
        }
        cpcommit();
    };

    float o[8][4];
    #pragma unroll
    for (int j = 0; j < 8; j++)
        #pragma unroll
        for (int e = 0; e < 4; e++) o[j][e] = 0.f;
    float mrow[2] = {-1e30f, -1e30f}, lrow[2] = {0.f, 0.f};

    int kend = 2*qt + 1;
    load_kv(0, 0);

    for (int kt = 0; kt <= kend; kt++) {
        int cur = kt & 1;
        if (kt < kend) load_kv(cur ^ 1, kt + 1);
        if (kt < kend) cpwait<1>(); else cpwait<0>();
        __syncthreads();

        bf16* sKh = dyn + cur*ASTG;
        bf16* sKl = sKh + KSZ;
        bf16* sVh = sKl + KSZ;
        bf16* sVl = sVh + KSZ;

        // S = Q K^T (hi*hi + hi*lo + lo*hi)
        float s[8][4];
        #pragma unroll
        for (int j = 0; j < 8; j++)
            #pragma unroll
            for (int e = 0; e < 4; e++) s[j][e] = 0.f;
        #pragma unroll
        for (int kk = 0; kk < 4; kk++) {
            #pragma unroll
            for (int p2 = 0; p2 < 4; p2++) {
                uint32_t kfh[4], kfl[4];
                int nrow = p2*16 + lc*8 + (lane & 7);
                int koff = kk*16 + ((lane >> 3) & 1)*8;
                ldm_x4(kfh, smaddr(sKh + nrow*72 + koff));
                ldm_x4(kfl, smaddr(sKl + nrow*72 + koff));
                mma16816(s[2*p2],   qh[kk], kfh[0], kfh[1]);
                mma16816(s[2*p2],   qh[kk], kfl[0], kfl[1]);
                mma16816(s[2*p2],   ql[kk], kfh[0], kfh[1]);
                mma16816(s[2*p2+1], qh[kk], kfh[2], kfh[3]);
                mma16816(s[2*p2+1], qh[kk], kfl[2], kfl[3]);
                mma16816(s[2*p2+1], ql[kk], kfh[2], kfh[3]);
            }
        }

        if (kt >= 2*qt) {
            int rowb = qt*128 + w*16 + (lane >> 2);
            int colb = kt*64 + ((lane & 3) << 1);
            #pragma unroll
            for (int j = 0; j < 8; j++)
                #pragma unroll
                for (int e = 0; e < 4; e++) {
                    int row = rowb + (e >> 1)*8;
                    int col = colb + j*8 + (e & 1);
                    if (col > row) s[j][e] = -1e30f;
                }
        }

        // online softmax
        #pragma unroll
        for (int e = 0; e < 2; e++) {
            float mx = -1e30f;
            #pragma unroll
            for (int j = 0; j < 8; j++)
                mx = fmaxf(mx, fmaxf(s[j][2*e], s[j][2*e+1]));
            mx = fmaxf(mx, __shfl_xor_sync(0xffffffffu, mx, 1));
            mx = fmaxf(mx, __shfl_xor_sync(0xffffffffu, mx, 2));
            float mn = fmaxf(mrow[e], mx);
            float corr = __expf(mrow[e] - mn);
            mrow[e] = mn;
            float sum = 0.f;
            #pragma unroll
            for (int j = 0; j < 8; j++) {
                float p0 = __expf(s[j][2*e]   - mn);
                float p1 = __expf(s[j][2*e+1] - mn);
                s[j][2*e] = p0; s[j][2*e+1] = p1;
                sum += p0 + p1;
            }
            sum += __shfl_xor_sync(0xffffffffu, sum, 1);
            sum += __shfl_xor_sync(0xffffffffu, sum, 2);
            lrow[e] = lrow[e]*corr + sum;
            #pragma unroll
            for (int j = 0; j < 8; j++) { o[j][2*e] *= corr; o[j][2*e+1] *= corr; }
        }

        // O += P V (split)
        #pragma unroll
        for (int kk = 0; kk < 4; kk++) {
            uint32_t ph[4], pl[4];
            #pragma unroll
            for (int u = 0; u < 2; u++) {
                float x0=s[2*kk+u][0], x1=s[2*kk+u][1], x2=s[2*kk+u][2], x3=s[2*kk+u][3];
                bf16 h0=__float2bfloat16(x0), h1=__float2bfloat16(x1);
                bf16 h2=__float2bfloat16(x2), h3=__float2bfloat16(x3);
                ph[2*u]   = pk2(h0, h1);
                ph[2*u+1] = pk2(h2, h3);
                pl[2*u]   = pkf2(x0-__bfloat162float(h0), x1-__bfloat162float(h1));
                pl[2*u+1] = pkf2(x2-__bfloat162float(h2), x3-__bfloat162float(h3));
            }
            #pragma unroll
            for (int p2 = 0; p2 < 4; p2++) {
                uint32_t vfh[4], vfl[4];
                int ro = (kk*16 + lr)*72 + p2*16 + lc*8;
                ldm_x4t(vfh, smaddr(sVh + ro));
                ldm_x4t(vfl, smaddr(sVl + ro));
                mma16816(o[2*p2],   ph, vfh[0], vfh[1]);
                mma16816(o[2*p2],   ph, vfl[0], vfl[1]);
                mma16816(o[2*p2],   pl, vfh[0], vfh[1]);
                mma16816(o[2*p2+1], ph, vfh[2], vfh[3]);
                mma16816(o[2*p2+1], ph, vfl[2], vfl[3]);
                mma16816(o[2*p2+1], pl, vfh[2], vfh[3]);
            }
        }
        __syncthreads();
    }

    // epilogue
    int b = bh >> 4, h = bh & 15;
    #pragma unroll
    for (int e = 0; e < 2; e++) {
        float inv = 1.f / lrow[e];
        int t = qt*128 + w*16 + (lane >> 2) + e*8;
        bf16* yh = g_yh + ((size_t)b*T_ + t)*C_ + h*64;
        bf16* yl = g_yl + ((size_t)b*T_ + t)*C_ + h*64;
        #pragma unroll
        for (int j = 0; j < 8; j++) {
            int d = j*8 + ((lane & 3) << 1);
            float v0 = o[j][2*e]*inv, v1 = o[j][2*e+1]*inv;
            bf16 h0 = __float2bfloat16(v0), h1 = __float2bfloat16(v1);
            *(uint32_t*)(yh + d) = pk2(h0, h1);
            *(uint32_t*)(yl + d) = pkf2(v0-__bfloat162float(h0), v1-__bfloat162float(h1));
        }
    }
}

// ---------------------------------------------------------------------------
extern "C" void kernel_launch(void* const* d_in, const int* in_sizes, int n_in,
                              void* d_out, int out_size)
{
    const float* x      = (const float*)d_in[0];
    const float* w_attn = (const float*)d_in[1];
    const float* b_attn = (const float*)d_in[2];
    const float* w_proj = (const float*)d_in[3];
    const float* b_proj = (const float*)d_in[4];
    float* out = (float*)d_out;
    (void)in_sizes; (void)n_in; (void)out_size;

    static int inited = 0;
    if (!inited) {
        cudaFuncSetAttribute(gemm_split_kernel,
            cudaFuncAttributeMaxDynamicSharedMemorySize, 2*GSTG*2);
        cudaFuncSetAttribute(attn_kernel,
            cudaFuncAttributeMaxDynamicSharedMemorySize, 2*ASTG*2);
        inited = 1;
    }

    split_kernel<<<8192, 256>>>((const float4*)x,      0, 2097152);
    split_kernel<<<3072, 256>>>((const float4*)w_attn, 1,  786432);
    split_kernel<<<1024, 256>>>((const float4*)w_proj, 2,  262144);
    gemm_split_kernel<<<dim3(24, 64), 256, 2*GSTG*2>>>(0, b_attn, nullptr);
    attn_kernel<<<dim3(16, 64), 256, 2*ASTG*2>>>();
    gemm_split_kernel<<<dim3(8, 64), 256, 2*GSTG*2>>>(1, b_proj, out);
}

// round 9
// speedup vs baseline: 5.2743x; 2.0108x over previous
#include <cuda_runtime.h>
#include <cuda_fp16.h>
#include <cstdint>

#define B_   4
#define T_   2048
#define C_   1024
#define H_   16
#define D_   64
#define BH_  64
#define M_   8192

typedef __half fp16;

// ---------------- scratch (allocation-free) ----------------
__device__ fp16 g_x [(size_t)M_*C_];
__device__ fp16 g_wa[(size_t)C_*3*C_];           // [K,N]
__device__ fp16 g_wp[(size_t)C_*C_];
__device__ fp16 g_qkv[(size_t)3*BH_*T_*D_];      // [part][bh][t][d], q pre-scaled
__device__ fp16 g_y [(size_t)M_*C_];

#define DI static __device__ __forceinline__

DI uint32_t smaddr(const void* p){ return (uint32_t)__cvta_generic_to_shared(p); }

DI void cpa16(void* dst, const void* src){
    asm volatile("cp.async.cg.shared.global [%0],[%1],16;\n"
        ::"r"(smaddr(dst)),"l"(src));
}
DI void cpcommit(){ asm volatile("cp.async.commit_group;\n"); }
template<int N> DI void cpwait(){ asm volatile("cp.async.wait_group %0;\n"::"n"(N)); }

DI void ldm_x4(uint32_t* r, uint32_t a){
    asm volatile("ldmatrix.sync.aligned.m8n8.x4.shared.b16 {%0,%1,%2,%3},[%4];"
        :"=r"(r[0]),"=r"(r[1]),"=r"(r[2]),"=r"(r[3]):"r"(a));
}
DI void ldm_x4t(uint32_t* r, uint32_t a){
    asm volatile("ldmatrix.sync.aligned.m8n8.x4.trans.shared.b16 {%0,%1,%2,%3},[%4];"
        :"=r"(r[0]),"=r"(r[1]),"=r"(r[2]),"=r"(r[3]):"r"(a));
}
DI void mma16816(float* c, const uint32_t* a, uint32_t b0, uint32_t b1){
    asm volatile("mma.sync.aligned.m16n8k16.row.col.f32.f16.f16.f32 "
        "{%0,%1,%2,%3},{%4,%5,%6,%7},{%8,%9},{%0,%1,%2,%3};"
        :"+f"(c[0]),"+f"(c[1]),"+f"(c[2]),"+f"(c[3])
        :"r"(a[0]),"r"(a[1]),"r"(a[2]),"r"(a[3]),"r"(b0),"r"(b1));
}
DI uint32_t pkf2(float x, float y){
    __half2 t = __floats2half2_rn(x, y);
    return *reinterpret_cast<uint32_t*>(&t);
}

// ---------------------------------------------------------------------------
// fp32 -> fp16 convert.  Destination resolved IN DEVICE CODE (never pass a
// __device__ global as a host-side kernel argument).
// mode: 0=x, 1=w_attn, 2=w_proj
// ---------------------------------------------------------------------------
__global__ void cvt_kernel(const float4* __restrict__ src, int mode)
{
    fp16* dst = (mode == 0) ? g_x : (mode == 1) ? g_wa : g_wp;
    int i = blockIdx.x*256 + threadIdx.x;
    float4 v = src[i];
    *reinterpret_cast<uint2*>(dst + (size_t)i*4) =
        make_uint2(pkf2(v.x, v.y), pkf2(v.z, v.w));
}

// ---------------------------------------------------------------------------
// fp16 GEMM via mma.sync.  128x128 tile, BK=32, 8 warps (2x4), warp 64x32,
// 2-stage cp.async pipeline (R4-proven structure).
// mode 0: x @ W_attn -> qkv scatter (bias, q scaled 1/8)
// mode 1: y @ W_proj -> fp32 out + bias
// ---------------------------------------------------------------------------
#define ASZ (128*40)
#define BSZ (32*136)
#define GSTG (ASZ + BSZ)          // halves per stage
#define GSMEM (2*GSTG*2)          // 37888 bytes, 2 stages

__global__ void __launch_bounds__(256,1) gemm_kernel(
    int mode, const float* __restrict__ bias, float* __restrict__ out)
{
    const int N = mode ? 1024 : 3072;
    const fp16* __restrict__ A = mode ? g_y  : g_x;
    const fp16* __restrict__ Bm = mode ? g_wp : g_wa;

    extern __shared__ fp16 dyn[];

    int tid = threadIdx.x, lane = tid & 31, wid = tid >> 5;
    int wm = wid >> 2, wn = wid & 3;
    int m0 = blockIdx.y * 128, n0 = blockIdx.x * 128;

    float acc[4][4][4];
    #pragma unroll
    for (int a = 0; a < 4; a++)
        #pragma unroll
        for (int b = 0; b < 4; b++)
            #pragma unroll
            for (int c = 0; c < 4; c++) acc[a][b][c] = 0.f;

    int lr = lane & 15, lc = lane >> 4;
    int ar = tid >> 1, aoff = (tid & 1) << 4;
    int br = tid >> 4, boff = (tid & 15) << 3;

    auto load_stage = [&](int st, int k0){
        fp16* sA = dyn + st*GSTG;
        fp16* sB = sA + ASZ;
        size_t asrc = (size_t)(m0 + ar)*1024 + k0 + aoff;
        cpa16(sA + ar*40 + aoff,     A + asrc);
        cpa16(sA + ar*40 + aoff + 8, A + asrc + 8);
        size_t bsrc = (size_t)(k0 + br)*N + n0 + boff;
        cpa16(sB + br*136 + boff,      Bm + bsrc);
        cpa16(sB + (br+16)*136 + boff, Bm + bsrc + (size_t)16*N);
        cpcommit();
    };

    load_stage(0, 0);

    for (int t = 0; t < 32; t++) {
        int cur = t & 1;
        if (t < 31) load_stage(cur ^ 1, (t+1)*32);
        if (t < 31) cpwait<1>(); else cpwait<0>();
        __syncthreads();

        fp16* sA = dyn + cur*GSTG;
        fp16* sB = sA + ASZ;

        #pragma unroll
        for (int kk = 0; kk < 32; kk += 16) {
            uint32_t af[4][4], bf[4][2];
            #pragma unroll
            for (int mi = 0; mi < 4; mi++)
                ldm_x4(af[mi], smaddr(sA + (wm*64 + mi*16 + lr)*40 + kk + lc*8));
            #pragma unroll
            for (int p = 0; p < 2; p++) {
                uint32_t tt[4];
                ldm_x4t(tt, smaddr(sB + (kk + lr)*136 + wn*32 + p*16 + lc*8));
                bf[2*p][0]=tt[0]; bf[2*p][1]=tt[1];
                bf[2*p+1][0]=tt[2]; bf[2*p+1][1]=tt[3];
            }
            #pragma unroll
            for (int mi = 0; mi < 4; mi++)
                #pragma unroll
                for (int ni = 0; ni < 4; ni++)
                    mma16816(acc[mi][ni], af[mi], bf[ni][0], bf[ni][1]);
        }
        __syncthreads();
    }

    int lr4 = lane >> 2, lc2 = (lane & 3) << 1;
    if (mode == 0) {
        #pragma unroll
        for (int mi = 0; mi < 4; mi++) {
            int r0 = m0 + wm*64 + mi*16 + lr4;
            #pragma unroll
            for (int ni = 0; ni < 4; ni++) {
                int col = n0 + wn*32 + ni*8 + lc2;
                float b0v = bias[col], b1v = bias[col+1];
                int part = col >> 10, within = col & 1023;
                int h = within >> 6, d = within & 63;
                float sc = (part == 0) ? 0.125f : 1.0f;
                #pragma unroll
                for (int e = 0; e < 2; e++) {
                    int r = r0 + e*8;
                    int bb = r >> 11, tt2 = r & 2047;
                    size_t idx = (((size_t)part*BH_ + bb*H_ + h)*T_ + tt2)*D_ + d;
                    *(uint32_t*)(g_qkv + idx) =
                        pkf2((acc[mi][ni][2*e]   + b0v)*sc,
                             (acc[mi][ni][2*e+1] + b1v)*sc);
                }
            }
        }
    } else {
        #pragma unroll
        for (int mi = 0; mi < 4; mi++) {
            int r0 = m0 + wm*64 + mi*16 + lr4;
            #pragma unroll
            for (int ni = 0; ni < 4; ni++) {
                int col = n0 + wn*32 + ni*8 + lc2;
                float b0v = bias[col], b1v = bias[col+1];
                #pragma unroll
                for (int e = 0; e < 2; e++) {
                    int r = r0 + e*8;
                    *(float2*)(out + (size_t)r*1024 + col) =
                        make_float2(acc[mi][ni][2*e] + b0v,
                                    acc[mi][ni][2*e+1] + b1v);
                }
            }
        }
    }
}

// ---------------------------------------------------------------------------
// FlashAttention-2, fp16 mma.sync, 2-stage cp.async K/V pipeline.
// 128-row Q tile, 8 warps (16 rows each), 64-wide K/V tiles, P in registers.
// ---------------------------------------------------------------------------
#define KSZ (64*72)
#define ASTG (2*KSZ)    // k, v per stage; 2 stages = 36864 bytes

__global__ void __launch_bounds__(256,1) attn_kernel()
{
    extern __shared__ fp16 dyn[];

    int tid = threadIdx.x, lane = tid & 31, w = tid >> 5;
    int qt = 15 - (int)blockIdx.x;
    int bh = blockIdx.y;

    const fp16* Qg = g_qkv + (size_t)bh*T_*D_ + (size_t)qt*128*D_;
    const fp16* Kg = g_qkv + ((size_t)BH_   + bh)*T_*D_;
    const fp16* Vg = g_qkv + ((size_t)2*BH_ + bh)*T_*D_;

    fp16* sQ = dyn;
    #pragma unroll
    for (int q = 0; q < 4; q++) {
        int c = tid + q*256;
        int r = c >> 3, off = (c & 7) << 3;
        cpa16(sQ + r*72 + off, Qg + (size_t)r*64 + off);
    }
    cpcommit();
    cpwait<0>();
    __syncthreads();

    int lr = lane & 15, lc = lane >> 4;
    uint32_t qf[4][4];
    #pragma unroll
    for (int kk = 0; kk < 4; kk++)
        ldm_x4(qf[kk], smaddr(sQ + (w*16 + lr)*72 + kk*16 + lc*8));
    __syncthreads();

    auto load_kv = [&](int st, int kt){
        fp16* sK = dyn + st*ASTG;
        fp16* sV = sK + KSZ;
        size_t base = (size_t)kt*64*D_;
        #pragma unroll
        for (int q = 0; q < 2; q++) {
            int c = tid + q*256;
            int r = c >> 3, off = (c & 7) << 3;
            size_t s = base + (size_t)r*64 + off;
            int ds = r*72 + off;
            cpa16(sK + ds, Kg + s);
            cpa16(sV + ds, Vg + s);
        }
        cpcommit();
    };

    float o[8][4];
    #pragma unroll
    for (int j = 0; j < 8; j++)
        #pragma unroll
        for (int e = 0; e < 4; e++) o[j][e] = 0.f;
    float mrow[2] = {-1e30f, -1e30f}, lrow[2] = {0.f, 0.f};

    int kend = 2*qt + 1;
    load_kv(0, 0);

    for (int kt = 0; kt <= kend; kt++) {
        int cur = kt & 1;
        if (kt < kend) load_kv(cur ^ 1, kt + 1);
        if (kt < kend) cpwait<1>(); else cpwait<0>();
        __syncthreads();

        fp16* sK = dyn + cur*ASTG;
        fp16* sV = sK + KSZ;

        float s[8][4];
        #pragma unroll
        for (int j = 0; j < 8; j++)
            #pragma unroll
            for (int e = 0; e < 4; e++) s[j][e] = 0.f;
        #pragma unroll
        for (int kk = 0; kk < 4; kk++) {
            #pragma unroll
            for (int p2 = 0; p2 < 4; p2++) {
                uint32_t kf[4];
                int nrow = p2*16 + lc*8 + (lane & 7);
                int koff = kk*16 + ((lane >> 3) & 1)*8;
                ldm_x4(kf, smaddr(sK + nrow*72 + koff));
                mma16816(s[2*p2],   qf[kk], kf[0], kf[1]);
                mma16816(s[2*p2+1], qf[kk], kf[2], kf[3]);
            }
        }

        if (kt >= 2*qt) {
            int rowb = qt*128 + w*16 + (lane >> 2);
            int colb = kt*64 + ((lane & 3) << 1);
            #pragma unroll
            for (int j = 0; j < 8; j++)
                #pragma unroll
                for (int e = 0; e < 4; e++) {
                    int row = rowb + (e >> 1)*8;
                    int col = colb + j*8 + (e & 1);
                    if (col > row) s[j][e] = -1e30f;
                }
        }

        #pragma unroll
        for (int e = 0; e < 2; e++) {
            float mx = -1e30f;
            #pragma unroll
            for (int j = 0; j < 8; j++)
                mx = fmaxf(mx, fmaxf(s[j][2*e], s[j][2*e+1]));
            mx = fmaxf(mx, __shfl_xor_sync(0xffffffffu, mx, 1));
            mx = fmaxf(mx, __shfl_xor_sync(0xffffffffu, mx, 2));
            float mn = fmaxf(mrow[e], mx);
            float corr = __expf(mrow[e] - mn);
            mrow[e] = mn;
            float sum = 0.f;
            #pragma unroll
            for (int j = 0; j < 8; j++) {
                float p0 = __expf(s[j][2*e]   - mn);
                float p1 = __expf(s[j][2*e+1] - mn);
                s[j][2*e] = p0; s[j][2*e+1] = p1;
                sum += p0 + p1;
            }
            sum += __shfl_xor_sync(0xffffffffu, sum, 1);
            sum += __shfl_xor_sync(0xffffffffu, sum, 2);
            lrow[e] = lrow[e]*corr + sum;
            #pragma unroll
            for (int j = 0; j < 8; j++) { o[j][2*e] *= corr; o[j][2*e+1] *= corr; }
        }

        #pragma unroll
        for (int kk = 0; kk < 4; kk++) {
            uint32_t pf[4];
            #pragma unroll
            for (int u = 0; u < 2; u++) {
                pf[2*u]   = pkf2(s[2*kk+u][0], s[2*kk+u][1]);
                pf[2*u+1] = pkf2(s[2*kk+u][2], s[2*kk+u][3]);
            }
            #pragma unroll
            for (int p2 = 0; p2 < 4; p2++) {
                uint32_t vf[4];
                ldm_x4t(vf, smaddr(sV + (kk*16 + lr)*72 + p2*16 + lc*8));
                mma16816(o[2*p2],   pf, vf[0], vf[1]);
                mma16816(o[2*p2+1], pf, vf[2], vf[3]);
            }
        }
        __syncthreads();
    }

    int b = bh >> 4, h = bh & 15;
    #pragma unroll
    for (int e = 0; e < 2; e++) {
        float inv = 1.f / lrow[e];
        int t = qt*128 + w*16 + (lane >> 2) + e*8;
        fp16* y = g_y + ((size_t)b*T_ + t)*C_ + h*64;
        #pragma unroll
        for (int j = 0; j < 8; j++) {
            int d = j*8 + ((lane & 3) << 1);
            *(uint32_t*)(y + d) = pkf2(o[j][2*e]*inv, o[j][2*e+1]*inv);
        }
    }
}

// ---------------------------------------------------------------------------
extern "C" void kernel_launch(void* const* d_in, const int* in_sizes, int n_in,
                              void* d_out, int out_size)
{
    const float* x      = (const float*)d_in[0];
    const float* w_attn = (const float*)d_in[1];
    const float* b_attn = (const float*)d_in[2];
    const float* w_proj = (const float*)d_in[3];
    const float* b_proj = (const float*)d_in[4];
    float* out = (float*)d_out;
    (void)in_sizes; (void)n_in; (void)out_size;

    cvt_kernel<<<8192, 256>>>((const float4*)x,      0);
    cvt_kernel<<<3072, 256>>>((const float4*)w_attn, 1);
    cvt_kernel<<<1024, 256>>>((const float4*)w_proj, 2);
    gemm_kernel<<<dim3(24, 64), 256, GSMEM>>>(0, b_attn, nullptr);
    attn_kernel<<<dim3(16, 64), 256, 2*ASTG*2>>>();
    gemm_kernel<<<dim3(8, 64), 256, GSMEM>>>(1, b_proj, out);
}

// round 10
// speedup vs baseline: 6.0980x; 1.1562x over previous
#include <cuda_runtime.h>
#include <cuda_fp16.h>
#include <cstdint>

#define B_   4
#define T_   2048
#define C_   1024
#define H_   16
#define D_   64
#define BH_  64
#define M_   8192

typedef __half fp16;

// ---------------- scratch (allocation-free) ----------------
__device__ fp16 g_x [(size_t)M_*C_];
__device__ fp16 g_wa[(size_t)C_*3*C_];           // [K,N]
__device__ fp16 g_wp[(size_t)C_*C_];
__device__ fp16 g_qkv[(size_t)3*BH_*T_*D_];      // [part][bh][t][d], q pre-scaled
__device__ fp16 g_y [(size_t)M_*C_];

#define DI static __device__ __forceinline__

DI uint32_t smaddr(const void* p){ return (uint32_t)__cvta_generic_to_shared(p); }

DI void cpa16(void* dst, const void* src){
    asm volatile("cp.async.cg.shared.global [%0],[%1],16;\n"
        ::"r"(smaddr(dst)),"l"(src));
}
DI void cpcommit(){ asm volatile("cp.async.commit_group;\n"); }
template<int N> DI void cpwait(){ asm volatile("cp.async.wait_group %0;\n"::"n"(N)); }

DI void ldm_x4(uint32_t* r, uint32_t a){
    asm volatile("ldmatrix.sync.aligned.m8n8.x4.shared.b16 {%0,%1,%2,%3},[%4];"
        :"=r"(r[0]),"=r"(r[1]),"=r"(r[2]),"=r"(r[3]):"r"(a));
}
DI void ldm_x4t(uint32_t* r, uint32_t a){
    asm volatile("ldmatrix.sync.aligned.m8n8.x4.trans.shared.b16 {%0,%1,%2,%3},[%4];"
        :"=r"(r[0]),"=r"(r[1]),"=r"(r[2]),"=r"(r[3]):"r"(a));
}
DI void mma16816(float* c, const uint32_t* a, uint32_t b0, uint32_t b1){
    asm volatile("mma.sync.aligned.m16n8k16.row.col.f32.f16.f16.f32 "
        "{%0,%1,%2,%3},{%4,%5,%6,%7},{%8,%9},{%0,%1,%2,%3};"
        :"+f"(c[0]),"+f"(c[1]),"+f"(c[2]),"+f"(c[3])
        :"r"(a[0]),"r"(a[1]),"r"(a[2]),"r"(a[3]),"r"(b0),"r"(b1));
}
DI uint32_t pkf2(float x, float y){
    __half2 t = __floats2half2_rn(x, y);
    return *reinterpret_cast<uint32_t*>(&t);
}

// ---------------------------------------------------------------------------
// fp32 -> fp16 convert.  Destination resolved in device code.
// mode: 0=x, 1=w_attn, 2=w_proj
// ---------------------------------------------------------------------------
__global__ void cvt_kernel(const float4* __restrict__ src, int mode)
{
    fp16* dst = (mode == 0) ? g_x : (mode == 1) ? g_wa : g_wp;
    int i = blockIdx.x*256 + threadIdx.x;
    float4 v = src[i];
    *reinterpret_cast<uint2*>(dst + (size_t)i*4) =
        make_uint2(pkf2(v.x, v.y), pkf2(v.z, v.w));
}

// ---------------------------------------------------------------------------
// fp16 GEMM via mma.sync.  128x128 tile, BK=32, 512 threads / 16 warps (4x4),
// warp tile 32x32 (low reg pressure -> 16 warps/SM), 3-stage cp.async pipeline.
// mode 0: x @ W_attn -> qkv scatter (bias, q scaled 1/8)
// mode 1: y @ W_proj -> fp32 out + bias
// ---------------------------------------------------------------------------
#define ASZ (128*40)
#define BSZ (32*136)
#define GSTG (ASZ + BSZ)          // halves per stage
#define GSMEM (3*GSTG*2)          // 56832 bytes, 3 stages

__global__ void __launch_bounds__(512,1) gemm_kernel(
    int mode, const float* __restrict__ bias, float* __restrict__ out)
{
    const int N = mode ? 1024 : 3072;
    const fp16* __restrict__ A = mode ? g_y  : g_x;
    const fp16* __restrict__ Bm = mode ? g_wp : g_wa;

    extern __shared__ fp16 dyn[];

    int tid = threadIdx.x, lane = tid & 31, wid = tid >> 5;   // 16 warps
    int wm = wid >> 2, wn = wid & 3;                          // 4x4
    int m0 = blockIdx.y * 128, n0 = blockIdx.x * 128;

    float acc[2][4][4];
    #pragma unroll
    for (int a = 0; a < 2; a++)
        #pragma unroll
        for (int b = 0; b < 4; b++)
            #pragma unroll
            for (int c = 0; c < 4; c++) acc[a][b][c] = 0.f;

    int lr = lane & 15, lc = lane >> 4;
    int ar = tid >> 2, aoff = (tid & 3) << 3;       // 128 rows x 32 cols, 1x16B
    int br = tid >> 4, boff = (tid & 15) << 3;      // 32 rows x 128 cols, 1x16B

    auto load_stage = [&](int st, int k0){
        fp16* sA = dyn + st*GSTG;
        fp16* sB = sA + ASZ;
        cpa16(sA + ar*40 + aoff, A + (size_t)(m0 + ar)*1024 + k0 + aoff);
        cpa16(sB + br*136 + boff, Bm + (size_t)(k0 + br)*N + n0 + boff);
        cpcommit();
    };

    load_stage(0, 0);
    load_stage(1, 32);

    for (int t = 0; t < 32; t++) {
        int cur = t % 3;
        if (t + 2 < 32) load_stage((t+2) % 3, (t+2)*32);
        if (t + 2 < 32) cpwait<2>();
        else if (t + 1 < 32) cpwait<1>();
        else cpwait<0>();
        __syncthreads();

        fp16* sA = dyn + cur*GSTG;
        fp16* sB = sA + ASZ;

        #pragma unroll
        for (int kk = 0; kk < 32; kk += 16) {
            uint32_t af[2][4], bf[4][2];
            #pragma unroll
            for (int mi = 0; mi < 2; mi++)
                ldm_x4(af[mi], smaddr(sA + (wm*32 + mi*16 + lr)*40 + kk + lc*8));
            #pragma unroll
            for (int p = 0; p < 2; p++) {
                uint32_t tt[4];
                ldm_x4t(tt, smaddr(sB + (kk + lr)*136 + wn*32 + p*16 + lc*8));
                bf[2*p][0]=tt[0]; bf[2*p][1]=tt[1];
                bf[2*p+1][0]=tt[2]; bf[2*p+1][1]=tt[3];
            }
            #pragma unroll
            for (int mi = 0; mi < 2; mi++)
                #pragma unroll
                for (int ni = 0; ni < 4; ni++)
                    mma16816(acc[mi][ni], af[mi], bf[ni][0], bf[ni][1]);
        }
        __syncthreads();
    }

    int lr4 = lane >> 2, lc2 = (lane & 3) << 1;
    if (mode == 0) {
        #pragma unroll
        for (int mi = 0; mi < 2; mi++) {
            int r0 = m0 + wm*32 + mi*16 + lr4;
            #pragma unroll
            for (int ni = 0; ni < 4; ni++) {
                int col = n0 + wn*32 + ni*8 + lc2;
                float b0v = bias[col], b1v = bias[col+1];
                int part = col >> 10, within = col & 1023;
                int h = within >> 6, d = within & 63;
                float sc = (part == 0) ? 0.125f : 1.0f;
                #pragma unroll
                for (int e = 0; e < 2; e++) {
                    int r = r0 + e*8;
                    int bb = r >> 11, tt2 = r & 2047;
                    size_t idx = (((size_t)part*BH_ + bb*H_ + h)*T_ + tt2)*D_ + d;
                    *(uint32_t*)(g_qkv + idx) =
                        pkf2((acc[mi][ni][2*e]   + b0v)*sc,
                             (acc[mi][ni][2*e+1] + b1v)*sc);
                }
            }
        }
    } else {
        #pragma unroll
        for (int mi = 0; mi < 2; mi++) {
            int r0 = m0 + wm*32 + mi*16 + lr4;
            #pragma unroll
            for (int ni = 0; ni < 4; ni++) {
                int col = n0 + wn*32 + ni*8 + lc2;
                float b0v = bias[col], b1v = bias[col+1];
                #pragma unroll
                for (int e = 0; e < 2; e++) {
                    int r = r0 + e*8;
                    *(float2*)(out + (size_t)r*1024 + col) =
                        make_float2(acc[mi][ni][2*e] + b0v,
                                    acc[mi][ni][2*e+1] + b1v);
                }
            }
        }
    }
}

// ---------------------------------------------------------------------------
// FlashAttention-2, fp16 mma.sync, 2-stage cp.async K/V pipeline (R9-proven).
// 128-row Q tile, 8 warps (16 rows each), 64-wide K/V tiles, P in registers.
// ---------------------------------------------------------------------------
#define KSZ (64*72)
#define ASTG (2*KSZ)    // k, v per stage; 2 stages = 36864 bytes

__global__ void __launch_bounds__(256,1) attn_kernel()
{
    extern __shared__ fp16 dyn[];

    int tid = threadIdx.x, lane = tid & 31, w = tid >> 5;
    int qt = 15 - (int)blockIdx.x;
    int bh = blockIdx.y;

    const fp16* Qg = g_qkv + (size_t)bh*T_*D_ + (size_t)qt*128*D_;
    const fp16* Kg = g_qkv + ((size_t)BH_   + bh)*T_*D_;
    const fp16* Vg = g_qkv + ((size_t)2*BH_ + bh)*T_*D_;

    fp16* sQ = dyn;
    #pragma unroll
    for (int q = 0; q < 4; q++) {
        int c = tid + q*256;
        int r = c >> 3, off = (c & 7) << 3;
        cpa16(sQ + r*72 + off, Qg + (size_t)r*64 + off);
    }
    cpcommit();
    cpwait<0>();
    __syncthreads();

    int lr = lane & 15, lc = lane >> 4;
    uint32_t qf[4][4];
    #pragma unroll
    for (int kk = 0; kk < 4; kk++)
        ldm_x4(qf[kk], smaddr(sQ + (w*16 + lr)*72 + kk*16 + lc*8));
    __syncthreads();

    auto load_kv = [&](int st, int kt){
        fp16* sK = dyn + st*ASTG;
        fp16* sV = sK + KSZ;
        size_t base = (size_t)kt*64*D_;
        #pragma unroll
        for (int q = 0; q < 2; q++) {
            int c = tid + q*256;
            int r = c >> 3, off = (c & 7) << 3;
            size_t s = base + (size_t)r*64 + off;
            int ds = r*72 + off;
            cpa16(sK + ds, Kg + s);
            cpa16(sV + ds, Vg + s);
        }
        cpcommit();
    };

    float o[8][4];
    #pragma unroll
    for (int j = 0; j < 8; j++)
        #pragma unroll
        for (int e = 0; e < 4; e++) o[j][e] = 0.f;
    float mrow[2] = {-1e30f, -1e30f}, lrow[2] = {0.f, 0.f};

    int kend = 2*qt + 1;
    load_kv(0, 0);

    for (int kt = 0; kt <= kend; kt++) {
        int cur = kt & 1;
        if (kt < kend) load_kv(cur ^ 1, kt + 1);
        if (kt < kend) cpwait<1>(); else cpwait<0>();
        __syncthreads();

        fp16* sK = dyn + cur*ASTG;
        fp16* sV = sK + KSZ;

        float s[8][4];
        #pragma unroll
        for (int j = 0; j < 8; j++)
            #pragma unroll
            for (int e = 0; e < 4; e++) s[j][e] = 0.f;
        #pragma unroll
        for (int kk = 0; kk < 4; kk++) {
            #pragma unroll
            for (int p2 = 0; p2 < 4; p2++) {
                uint32_t kf[4];
                int nrow = p2*16 + lc*8 + (lane & 7);
                int koff = kk*16 + ((lane >> 3) & 1)*8;
                ldm_x4(kf, smaddr(sK + nrow*72 + koff));
                mma16816(s[2*p2],   qf[kk], kf[0], kf[1]);
                mma16816(s[2*p2+1], qf[kk], kf[2], kf[3]);
            }
        }

        if (kt >= 2*qt) {
            int rowb = qt*128 + w*16 + (lane >> 2);
            int colb = kt*64 + ((lane & 3) << 1);
            #pragma unroll
            for (int j = 0; j < 8; j++)
                #pragma unroll
                for (int e = 0; e < 4; e++) {
                    int row = rowb + (e >> 1)*8;
                    int col = colb + j*8 + (e & 1);
                    if (col > row) s[j][e] = -1e30f;
                }
        }

        #pragma unroll
        for (int e = 0; e < 2; e++) {
            float mx = -1e30f;
            #pragma unroll
            for (int j = 0; j < 8; j++)
                mx = fmaxf(mx, fmaxf(s[j][2*e], s[j][2*e+1]));
            mx = fmaxf(mx, __shfl_xor_sync(0xffffffffu, mx, 1));
            mx = fmaxf(mx, __shfl_xor_sync(0xffffffffu, mx, 2));
            float mn = fmaxf(mrow[e], mx);
            float corr = __expf(mrow[e] - mn);
            mrow[e] = mn;
            float sum = 0.f;
            #pragma unroll
            for (int j = 0; j < 8; j++) {
                float p0 = __expf(s[j][2*e]   - mn);
                float p1 = __expf(s[j][2*e+1] - mn);
                s[j][2*e] = p0; s[j][2*e+1] = p1;
                sum += p0 + p1;
            }
            sum += __shfl_xor_sync(0xffffffffu, sum, 1);
            sum += __shfl_xor_sync(0xffffffffu, sum, 2);
            lrow[e] = lrow[e]*corr + sum;
            #pragma unroll
            for (int j = 0; j < 8; j++) { o[j][2*e] *= corr; o[j][2*e+1] *= corr; }
        }

        #pragma unroll
        for (int kk = 0; kk < 4; kk++) {
            uint32_t pf[4];
            #pragma unroll
            for (int u = 0; u < 2; u++) {
                pf[2*u]   = pkf2(s[2*kk+u][0], s[2*kk+u][1]);
                pf[2*u+1] = pkf2(s[2*kk+u][2], s[2*kk+u][3]);
            }
            #pragma unroll
            for (int p2 = 0; p2 < 4; p2++) {
                uint32_t vf[4];
                ldm_x4t(vf, smaddr(sV + (kk*16 + lr)*72 + p2*16 + lc*8));
                mma16816(o[2*p2],   pf, vf[0], vf[1]);
                mma16816(o[2*p2+1], pf, vf[2], vf[3]);
            }
        }
        __syncthreads();
    }

    int b = bh >> 4, h = bh & 15;
    #pragma unroll
    for (int e = 0; e < 2; e++) {
        float inv = 1.f / lrow[e];
        int t = qt*128 + w*16 + (lane >> 2) + e*8;
        fp16* y = g_y + ((size_t)b*T_ + t)*C_ + h*64;
        #pragma unroll
        for (int j = 0; j < 8; j++) {
            int d = j*8 + ((lane & 3) << 1);
            *(uint32_t*)(y + d) = pkf2(o[j][2*e]*inv, o[j][2*e+1]*inv);
        }
    }
}

// ---------------------------------------------------------------------------
extern "C" void kernel_launch(void* const* d_in, const int* in_sizes, int n_in,
                              void* d_out, int out_size)
{
    const float* x      = (const float*)d_in[0];
    const float* w_attn = (const float*)d_in[1];
    const float* b_attn = (const float*)d_in[2];
    const float* w_proj = (const float*)d_in[3];
    const float* b_proj = (const float*)d_in[4];
    float* out = (float*)d_out;
    (void)in_sizes; (void)n_in; (void)out_size;

    cudaFuncSetAttribute(gemm_kernel,
        cudaFuncAttributeMaxDynamicSharedMemorySize, GSMEM);

    cvt_kernel<<<8192, 256>>>((const float4*)x,      0);
    cvt_kernel<<<3072, 256>>>((const float4*)w_attn, 1);
    cvt_kernel<<<1024, 256>>>((const float4*)w_proj, 2);
    gemm_kernel<<<dim3(24, 64), 512, GSMEM>>>(0, b_attn, nullptr);
    attn_kernel<<<dim3(16, 64), 256, 2*ASTG*2>>>();
    gemm_kernel<<<dim3(8, 64), 512, GSMEM>>>(1, b_proj, out);
}